// round 10
// baseline (speedup 1.0000x reference)
#include <cuda_runtime.h>
#include <cuda_fp16.h>
#include <cstdint>
#include <mma.h>

using namespace nvcuda;

// Problem dims
#define BATCH   2
#define SEQ     4096
#define DIN     512
#define DOUT    512
#define MTOT    (BATCH * SEQ)
#define QSCALE  0.04419417382415922f   // 1/sqrt(512)

// Projection GEMM tiling
#define BM 128
#define BN 128
#define BK 32
#define NTHREADS 256

// Flash attention config
#define FBM 32
#define FBN 64
#define FD  512
#define FDC 128
#define NBLK (SEQ / FBN)
#define FTHREADS 256

// smem layout (bytes)
#define SQ_STRIDE  520
#define SKV_STRIDE 136
#define SP_STRIDE  72
#define SQ_OFF   0
#define SQ_BYTES (FBM * SQ_STRIDE * 2)            // 33280
#define SKV_OFF  SQ_BYTES
#define SKV_BUF_BYTES (64 * SKV_STRIDE * 2)       // 17408
#define SP_OFF   (SKV_OFF + 4 * SKV_BUF_BYTES)    // 102912
#define SP_BYTES (FBM * SP_STRIDE * 2)            // 4608
#define MRUN_OFF (SP_OFF + SP_BYTES)              // 107520
#define LRUN_OFF (MRUN_OFF + 128)
#define WMAX_OFF (LRUN_OFF + 128)
#define WSUM_OFF (WMAX_OFF + 512)
#define SMEM_TOTAL (WSUM_OFF + 512)               // 108800

// Scratch (device globals)
__device__ __align__(128) __half g_Q[(size_t)MTOT * DOUT];
__device__ __align__(128) __half g_K[(size_t)MTOT * DOUT];
__device__ __align__(128) __half g_V[(size_t)MTOT * DOUT];

// ---------------------------------------------------------------------------
// PTX helpers
// ---------------------------------------------------------------------------
__device__ __forceinline__ uint32_t smem_u32(const void* p) {
    return (uint32_t)__cvta_generic_to_shared(p);
}

__device__ __forceinline__ void cp_async16(uint32_t dst, const void* src) {
    asm volatile("cp.async.cg.shared.global [%0], [%1], 16;" :: "r"(dst), "l"(src));
}

__device__ __forceinline__ void cp_commit() {
    asm volatile("cp.async.commit_group;");
}

__device__ __forceinline__ void cp_wait1() {
    asm volatile("cp.async.wait_group 1;");
}

__device__ __forceinline__ void ldm_x4(uint32_t& a0, uint32_t& a1, uint32_t& a2, uint32_t& a3,
                                       uint32_t addr) {
    asm volatile("ldmatrix.sync.aligned.m8n8.x4.shared.b16 {%0,%1,%2,%3}, [%4];"
                 : "=r"(a0), "=r"(a1), "=r"(a2), "=r"(a3) : "r"(addr));
}

__device__ __forceinline__ void ldm_x4_t(uint32_t& a0, uint32_t& a1, uint32_t& a2, uint32_t& a3,
                                         uint32_t addr) {
    asm volatile("ldmatrix.sync.aligned.m8n8.x4.trans.shared.b16 {%0,%1,%2,%3}, [%4];"
                 : "=r"(a0), "=r"(a1), "=r"(a2), "=r"(a3) : "r"(addr));
}

__device__ __forceinline__ void mma16816(float* d, uint32_t a0, uint32_t a1, uint32_t a2,
                                         uint32_t a3, uint32_t b0, uint32_t b1) {
    asm volatile("mma.sync.aligned.m16n8k16.row.col.f32.f16.f16.f32 "
                 "{%0,%1,%2,%3}, {%4,%5,%6,%7}, {%8,%9}, {%0,%1,%2,%3};"
                 : "+f"(d[0]), "+f"(d[1]), "+f"(d[2]), "+f"(d[3])
                 : "r"(a0), "r"(a1), "r"(a2), "r"(a3), "r"(b0), "r"(b1));
}

// K/V chunk loader. ch 0..3 = K d-chunks, 4..7 = V d-chunks; buffer = ch&3.
__device__ __forceinline__ void load_chunk(char* sm, const __half* Kb, const __half* Vb,
                                           int tid, int j, int ch) {
    const __half* src = (ch < 4) ? Kb : Vb;
    const int d0 = (ch & 3) * FDC;
    __half* dbuf = (__half*)(sm + SKV_OFF + (size_t)(ch & 3) * SKV_BUF_BYTES);
    const int n0 = j * FBN;
#pragma unroll
    for (int it = 0; it < 4; it++) {
        int idx = tid + it * FTHREADS;
        int r = idx >> 4;
        int c8 = idx & 15;
        cp_async16(smem_u32(&dbuf[r * SKV_STRIDE + c8 * 8]),
                   &src[(size_t)(n0 + r) * FD + d0 + c8 * 8]);
    }
}

// ---------------------------------------------------------------------------
// Kernel 1: fused projections (fp16 out; Q pre-scaled by QSCALE)
// Register-prefetch double buffering over BK=32.
// ---------------------------------------------------------------------------
__global__ void __launch_bounds__(NTHREADS, 2)
proj_kernel(const float* __restrict__ x,
            const float* __restrict__ Wq,
            const float* __restrict__ Wk,
            const float* __restrict__ Wv) {
    const int which = blockIdx.z;
    const float* W = (which == 0) ? Wq : ((which == 1) ? Wk : Wv);
    __half* outbuf = (which == 0) ? g_Q : ((which == 1) ? g_K : g_V);
    const float oscale = (which == 0) ? QSCALE : 1.0f;

    __shared__ __half sA[BM][BK + 8];
    __shared__ __half sB[BK][BN + 8];
    __shared__ float stage[8][16][20];

    const int m0 = blockIdx.y * BM;
    const int n0 = blockIdx.x * BN;
    const int tid = threadIdx.x;
    const int wid = tid >> 5;
    const int lane = tid & 31;
    const int wr = wid >> 2;
    const int wc = wid & 3;

    wmma::fragment<wmma::accumulator, 16, 16, 16, float> acc[4][2];
#pragma unroll
    for (int i = 0; i < 4; i++) {
#pragma unroll
        for (int j = 0; j < 2; j++) {
            wmma::fill_fragment(acc[i][j], 0.0f);
        }
    }

    // iteration 0: load + convert directly to smem
#pragma unroll
    for (int it = 0; it < 4; it++) {
        int u = tid + it * NTHREADS;
        int r = u >> 3;
        int g = u & 7;
        float4 v = *(const float4*)&x[(size_t)(m0 + r) * DIN + g * 4];
        *(__half2*)&sA[r][g * 4]     = __floats2half2_rn(v.x, v.y);
        *(__half2*)&sA[r][g * 4 + 2] = __floats2half2_rn(v.z, v.w);
    }
#pragma unroll
    for (int it = 0; it < 4; it++) {
        int u = tid + it * NTHREADS;
        int r = u >> 5;
        int g = u & 31;
        float4 v = *(const float4*)&W[(size_t)r * DOUT + n0 + g * 4];
        *(__half2*)&sB[r][g * 4]     = __floats2half2_rn(v.x, v.y);
        *(__half2*)&sB[r][g * 4 + 2] = __floats2half2_rn(v.z, v.w);
    }
    __syncthreads();

    float4 pa[4];
    float4 pb[4];

    for (int k0 = 0; k0 < DIN; k0 += BK) {
        const int kn = k0 + BK;
        if (kn < DIN) {
#pragma unroll
            for (int it = 0; it < 4; it++) {
                int u = tid + it * NTHREADS;
                int r = u >> 3;
                int g = u & 7;
                pa[it] = *(const float4*)&x[(size_t)(m0 + r) * DIN + kn + g * 4];
            }
#pragma unroll
            for (int it = 0; it < 4; it++) {
                int u = tid + it * NTHREADS;
                int r = u >> 5;
                int g = u & 31;
                pb[it] = *(const float4*)&W[(size_t)(kn + r) * DOUT + n0 + g * 4];
            }
        }

#pragma unroll
        for (int kk = 0; kk < BK; kk += 16) {
            wmma::fragment<wmma::matrix_a, 16, 16, 16, __half, wmma::row_major> af[4];
            wmma::fragment<wmma::matrix_b, 16, 16, 16, __half, wmma::row_major> bf[2];
#pragma unroll
            for (int i = 0; i < 4; i++) {
                wmma::load_matrix_sync(af[i], &sA[wr * 64 + i * 16][kk], BK + 8);
            }
#pragma unroll
            for (int j = 0; j < 2; j++) {
                wmma::load_matrix_sync(bf[j], &sB[kk][wc * 32 + j * 16], BN + 8);
            }
#pragma unroll
            for (int i = 0; i < 4; i++) {
#pragma unroll
                for (int j = 0; j < 2; j++) {
                    wmma::mma_sync(acc[i][j], af[i], bf[j], acc[i][j]);
                }
            }
        }
        __syncthreads();

        if (kn < DIN) {
#pragma unroll
            for (int it = 0; it < 4; it++) {
                int u = tid + it * NTHREADS;
                int r = u >> 3;
                int g = u & 7;
                *(__half2*)&sA[r][g * 4]     = __floats2half2_rn(pa[it].x, pa[it].y);
                *(__half2*)&sA[r][g * 4 + 2] = __floats2half2_rn(pa[it].z, pa[it].w);
            }
#pragma unroll
            for (int it = 0; it < 4; it++) {
                int u = tid + it * NTHREADS;
                int r = u >> 5;
                int g = u & 31;
                *(__half2*)&sB[r][g * 4]     = __floats2half2_rn(pb[it].x, pb[it].y);
                *(__half2*)&sB[r][g * 4 + 2] = __floats2half2_rn(pb[it].z, pb[it].w);
            }
            __syncthreads();
        }
    }

#pragma unroll
    for (int i = 0; i < 4; i++) {
#pragma unroll
        for (int j = 0; j < 2; j++) {
            wmma::store_matrix_sync(&stage[wid][0][0], acc[i][j], 20, wmma::mem_row_major);
            __syncwarp();
#pragma unroll
            for (int q = 0; q < 8; q++) {
                int e = lane * 8 + q;
                int r = e >> 4;
                int c = e & 15;
                size_t go = (size_t)(m0 + wr * 64 + i * 16 + r) * DOUT + (n0 + wc * 32 + j * 16 + c);
                outbuf[go] = __float2half(stage[wid][r][c] * oscale);
            }
            __syncwarp();
        }
    }
}

// ---------------------------------------------------------------------------
// Kernel 2: fused flash attention.  O = softmax(Q K^T) V, fp32 out.
// FBM=32, grid (SEQ/FBM, BATCH) = 256 CTAs, 2 CTAs/SM.
// 8 warps: rg = wid>>2 (16-row slab, 0..1), cg = wid&3 (16-col group, 0..3).
// ---------------------------------------------------------------------------
__global__ void __launch_bounds__(FTHREADS, 2)
flash_kernel(float* __restrict__ out) {
    extern __shared__ char smem[];
    __half* sQ  = (__half*)(smem + SQ_OFF);
    __half* sP  = (__half*)(smem + SP_OFF);
    float* mrun = (float*)(smem + MRUN_OFF);
    float* lrun = (float*)(smem + LRUN_OFF);
    float* wmax = (float*)(smem + WMAX_OFF);   // [4][32]
    float* wsum = (float*)(smem + WSUM_OFF);   // [4][32]

    const int b = blockIdx.y;
    const int m_base = blockIdx.x * FBM;
    const int tid = threadIdx.x;
    const int wid = tid >> 5;
    const int lane = tid & 31;
    const int rg = wid >> 2;     // 0..1
    const int cg = wid & 3;      // 0..3

    const __half* Qb = g_Q + (size_t)b * SEQ * FD;
    const __half* Kb = g_K + (size_t)b * SEQ * FD;
    const __half* Vb = g_V + (size_t)b * SEQ * FD;

    if (tid < FBM) {
        mrun[tid] = -1e30f;
        lrun[tid] = 0.0f;
    }

    // Load Q tile (one cp.async group): 32 rows x 64 8-half units = 2048
#pragma unroll
    for (int it = 0; it < 8; it++) {
        int idx = tid + it * FTHREADS;
        int r = idx >> 6;
        int c8 = idx & 63;
        cp_async16(smem_u32(&sQ[r * SQ_STRIDE + c8 * 8]),
                   &Qb[(size_t)(m_base + r) * FD + c8 * 8]);
    }
    cp_commit();

    load_chunk(smem, Kb, Vb, tid, 0, 0);
    cp_commit();
    load_chunk(smem, Kb, Vb, tid, 0, 1);
    cp_commit();

    float o[16][4];
#pragma unroll
    for (int i = 0; i < 16; i++) {
#pragma unroll
        for (int e = 0; e < 4; e++) {
            o[i][e] = 0.0f;
        }
    }

    const int r0 = rg * 16 + (lane >> 2);
    const int r1 = r0 + 8;

    for (int j = 0; j < NBLK; j++) {
        float s[2][4];
#pragma unroll
        for (int t = 0; t < 2; t++) {
#pragma unroll
            for (int e = 0; e < 4; e++) {
                s[t][e] = 0.0f;
            }
        }

#pragma unroll
        for (int cc = 0; cc < 8; cc++) {
            cp_wait1();
            __syncthreads();

            int pj = j;
            int pc = cc + 2;
            if (pc >= 8) {
                pj = j + 1;
                pc = pc - 8;
            }
            if (pj < NBLK) {
                load_chunk(smem, Kb, Vb, tid, pj, pc);
            }
            cp_commit();

            const __half* buf = (const __half*)(smem + SKV_OFF + (size_t)(cc & 3) * SKV_BUF_BYTES);

            if (cc < 4) {
                // ---- S += Q[:, chunk] * K[:, chunk]^T  (warp tile 16x16) ----
#pragma unroll
                for (int ks = 0; ks < 8; ks++) {
                    uint32_t a0, a1, a2, a3;
                    int arow = rg * 16 + (lane & 15);
                    int acol = cc * 128 + ks * 16 + ((lane & 16) >> 1);
                    ldm_x4(a0, a1, a2, a3, smem_u32(&sQ[arow * SQ_STRIDE + acol]));
                    uint32_t b0, b1, b2, b3;
                    int brow = cg * 16 + (lane & 7) + ((lane & 16) >> 1);
                    int bcol = ks * 16 + (lane & 8);
                    ldm_x4(b0, b1, b2, b3, smem_u32(&buf[brow * SKV_STRIDE + bcol]));
                    mma16816(s[0], a0, a1, a2, a3, b0, b1);
                    mma16816(s[1], a0, a1, a2, a3, b2, b3);
                }
                if (cc == 3) {
                    // ---- online softmax ----
                    float mx0 = fmaxf(fmaxf(s[0][0], s[0][1]), fmaxf(s[1][0], s[1][1]));
                    float mx1 = fmaxf(fmaxf(s[0][2], s[0][3]), fmaxf(s[1][2], s[1][3]));
                    mx0 = fmaxf(mx0, __shfl_xor_sync(0xffffffffu, mx0, 1));
                    mx0 = fmaxf(mx0, __shfl_xor_sync(0xffffffffu, mx0, 2));
                    mx1 = fmaxf(mx1, __shfl_xor_sync(0xffffffffu, mx1, 1));
                    mx1 = fmaxf(mx1, __shfl_xor_sync(0xffffffffu, mx1, 2));
                    if ((lane & 3) == 0) {
                        wmax[cg * 32 + r0] = mx0;
                        wmax[cg * 32 + r1] = mx1;
                    }
                    __syncthreads();
                    float mo0 = mrun[r0];
                    float mo1 = mrun[r1];
                    float mn0 = fmaxf(fmaxf(mo0, fmaxf(wmax[r0], wmax[32 + r0])),
                                      fmaxf(wmax[64 + r0], wmax[96 + r0]));
                    float mn1 = fmaxf(fmaxf(mo1, fmaxf(wmax[r1], wmax[32 + r1])),
                                      fmaxf(wmax[64 + r1], wmax[96 + r1]));
                    float al0 = __expf(mo0 - mn0);
                    float al1 = __expf(mo1 - mn1);
                    float sum0 = 0.0f;
                    float sum1 = 0.0f;
#pragma unroll
                    for (int t = 0; t < 2; t++) {
                        float p00 = __expf(s[t][0] - mn0);
                        float p01 = __expf(s[t][1] - mn0);
                        float p10 = __expf(s[t][2] - mn1);
                        float p11 = __expf(s[t][3] - mn1);
                        sum0 += p00 + p01;
                        sum1 += p10 + p11;
                        int col = cg * 16 + t * 8 + 2 * (lane & 3);
                        *(__half2*)&sP[r0 * SP_STRIDE + col] = __floats2half2_rn(p00, p01);
                        *(__half2*)&sP[r1 * SP_STRIDE + col] = __floats2half2_rn(p10, p11);
                    }
#pragma unroll
                    for (int i = 0; i < 16; i++) {
                        o[i][0] *= al0;
                        o[i][1] *= al0;
                        o[i][2] *= al1;
                        o[i][3] *= al1;
                    }
                    sum0 += __shfl_xor_sync(0xffffffffu, sum0, 1);
                    sum0 += __shfl_xor_sync(0xffffffffu, sum0, 2);
                    sum1 += __shfl_xor_sync(0xffffffffu, sum1, 1);
                    sum1 += __shfl_xor_sync(0xffffffffu, sum1, 2);
                    if ((lane & 3) == 0) {
                        wsum[cg * 32 + r0] = sum0;
                        wsum[cg * 32 + r1] = sum1;
                    }
                    __syncthreads();
                    if (cg == 0 && (lane & 3) == 0) {
                        lrun[r0] = lrun[r0] * al0 + wsum[r0] + wsum[32 + r0] + wsum[64 + r0] + wsum[96 + r0];
                        lrun[r1] = lrun[r1] * al1 + wsum[r1] + wsum[32 + r1] + wsum[64 + r1] + wsum[96 + r1];
                        mrun[r0] = mn0;
                        mrun[r1] = mn1;
                    }
                }
            } else {
                // ---- O[:, chunk] += P * V[:, chunk]  (warp cols cg*32..+32) ----
                const int c2 = cc - 4;
#pragma unroll
                for (int ks = 0; ks < 4; ks++) {
                    uint32_t a0, a1, a2, a3;
                    int arow = rg * 16 + (lane & 15);
                    int acol = ks * 16 + ((lane & 16) >> 1);
                    ldm_x4(a0, a1, a2, a3, smem_u32(&sP[arow * SP_STRIDE + acol]));
#pragma unroll
                    for (int nt2 = 0; nt2 < 2; nt2++) {
                        uint32_t b0, b1, b2, b3;
                        int brow = ks * 16 + (lane & 15);
                        int bcol = cg * 32 + nt2 * 16 + ((lane & 16) >> 1);
                        ldm_x4_t(b0, b1, b2, b3, smem_u32(&buf[brow * SKV_STRIDE + bcol]));
                        int t = c2 * 4 + nt2 * 2;
                        mma16816(o[t],     a0, a1, a2, a3, b0, b1);
                        mma16816(o[t + 1], a0, a1, a2, a3, b2, b3);
                    }
                }
            }
        }
    }

    // ---- epilogue: O /= l, store fp32 ----
    __syncthreads();
    float inv0 = 1.0f / lrun[r0];
    float inv1 = 1.0f / lrun[r1];
    float* Ob = out + ((size_t)b * SEQ + m_base) * FD;
#pragma unroll
    for (int c2 = 0; c2 < 4; c2++) {
#pragma unroll
        for (int nt = 0; nt < 4; nt++) {
            int t = c2 * 4 + nt;
            int col = c2 * 128 + cg * 32 + nt * 8 + 2 * (lane & 3);
            *(float2*)&Ob[(size_t)r0 * FD + col] = make_float2(o[t][0] * inv0, o[t][1] * inv0);
            *(float2*)&Ob[(size_t)r1 * FD + col] = make_float2(o[t][2] * inv1, o[t][3] * inv1);
        }
    }
}

// ---------------------------------------------------------------------------
extern "C" void kernel_launch(void* const* d_in, const int* in_sizes, int n_in,
                              void* d_out, int out_size) {
    const float* x  = (const float*)d_in[0];
    const float* Wq = (const float*)d_in[1];
    const float* Wk = (const float*)d_in[2];
    const float* Wv = (const float*)d_in[3];
    float* out = (float*)d_out;

    cudaFuncSetAttribute(flash_kernel, cudaFuncAttributeMaxDynamicSharedMemorySize, SMEM_TOTAL);

    dim3 gproj(DOUT / BN, MTOT / BM, 3);
    proj_kernel<<<gproj, NTHREADS>>>(x, Wq, Wk, Wv);

    dim3 gflash(SEQ / FBM, BATCH);   // (128, 2) = 256 CTAs
    flash_kernel<<<gflash, FTHREADS, SMEM_TOTAL>>>(out);
}

// round 11
// speedup vs baseline: 1.2736x; 1.2736x over previous
#include <cuda_runtime.h>
#include <cuda_fp16.h>
#include <cstdint>
#include <mma.h>

using namespace nvcuda;

// Problem dims
#define BATCH   2
#define SEQ     4096
#define DIN     512
#define DOUT    512
#define MTOT    (BATCH * SEQ)
#define QSCALE  0.04419417382415922f   // 1/sqrt(512)

// Projection GEMM tiling: 128x256 CTA tile, 512 threads, warp tile 32x64
#define PBM 128
#define PBN 256
#define PBK 32
#define PTHREADS 512
#define PA_STRIDE 40     // 32 + 8 (halves)
#define PB_STRIDE 264    // 256 + 8 (halves)
#define PA_BYTES (PBM * PA_STRIDE * 2)   // 10240
#define PB_BYTES (PBK * PB_STRIDE * 2)   // 16896
#define P_STAGE  (PA_BYTES + PB_BYTES)   // 27136
#define P_SMEM   (2 * P_STAGE)           // 54272

// Flash attention config (R9 proven: FBM=64)
#define FBM 64
#define FBN 64
#define FD  512
#define FDC 128
#define NBLK (SEQ / FBN)
#define FTHREADS 256

// flash smem layout (bytes)
#define SQ_STRIDE  520
#define SKV_STRIDE 136
#define SP_STRIDE  72
#define SQ_OFF   0
#define SQ_BYTES (FBM * SQ_STRIDE * 2)
#define SKV_OFF  SQ_BYTES
#define SKV_BUF_BYTES (64 * SKV_STRIDE * 2)
#define SP_OFF   (SKV_OFF + 4 * SKV_BUF_BYTES)
#define SP_BYTES (FBM * SP_STRIDE * 2)
#define MRUN_OFF (SP_OFF + SP_BYTES)
#define LRUN_OFF (MRUN_OFF + 256)
#define WMAX_OFF (LRUN_OFF + 256)
#define WSUM_OFF (WMAX_OFF + 512)
#define SMEM_TOTAL (WSUM_OFF + 512)

// Scratch (device globals)
__device__ __align__(128) __half g_X16[(size_t)MTOT * DIN];
__device__ __align__(128) __half g_W16[3][(size_t)DIN * DOUT];
__device__ __align__(128) __half g_Q[(size_t)MTOT * DOUT];
__device__ __align__(128) __half g_K[(size_t)MTOT * DOUT];
__device__ __align__(128) __half g_V[(size_t)MTOT * DOUT];

// ---------------------------------------------------------------------------
// PTX helpers
// ---------------------------------------------------------------------------
__device__ __forceinline__ uint32_t smem_u32(const void* p) {
    return (uint32_t)__cvta_generic_to_shared(p);
}

__device__ __forceinline__ void cp_async16(uint32_t dst, const void* src) {
    asm volatile("cp.async.cg.shared.global [%0], [%1], 16;" :: "r"(dst), "l"(src));
}

__device__ __forceinline__ void cp_commit() {
    asm volatile("cp.async.commit_group;");
}

__device__ __forceinline__ void cp_wait1() {
    asm volatile("cp.async.wait_group 1;");
}

__device__ __forceinline__ void ldm_x4(uint32_t& a0, uint32_t& a1, uint32_t& a2, uint32_t& a3,
                                       uint32_t addr) {
    asm volatile("ldmatrix.sync.aligned.m8n8.x4.shared.b16 {%0,%1,%2,%3}, [%4];"
                 : "=r"(a0), "=r"(a1), "=r"(a2), "=r"(a3) : "r"(addr));
}

__device__ __forceinline__ void ldm_x4_t(uint32_t& a0, uint32_t& a1, uint32_t& a2, uint32_t& a3,
                                         uint32_t addr) {
    asm volatile("ldmatrix.sync.aligned.m8n8.x4.trans.shared.b16 {%0,%1,%2,%3}, [%4];"
                 : "=r"(a0), "=r"(a1), "=r"(a2), "=r"(a3) : "r"(addr));
}

__device__ __forceinline__ void mma16816(float* d, uint32_t a0, uint32_t a1, uint32_t a2,
                                         uint32_t a3, uint32_t b0, uint32_t b1) {
    asm volatile("mma.sync.aligned.m16n8k16.row.col.f32.f16.f16.f32 "
                 "{%0,%1,%2,%3}, {%4,%5,%6,%7}, {%8,%9}, {%0,%1,%2,%3};"
                 : "+f"(d[0]), "+f"(d[1]), "+f"(d[2]), "+f"(d[3])
                 : "r"(a0), "r"(a1), "r"(a2), "r"(a3), "r"(b0), "r"(b1));
}

// K/V chunk loader. ch 0..3 = K d-chunks, 4..7 = V d-chunks; buffer = ch&3.
__device__ __forceinline__ void load_chunk(char* sm, const __half* Kb, const __half* Vb,
                                           int tid, int j, int ch) {
    const __half* src = (ch < 4) ? Kb : Vb;
    const int d0 = (ch & 3) * FDC;
    __half* dbuf = (__half*)(sm + SKV_OFF + (size_t)(ch & 3) * SKV_BUF_BYTES);
    const int n0 = j * FBN;
#pragma unroll
    for (int it = 0; it < 4; it++) {
        int idx = tid + it * FTHREADS;
        int r = idx >> 4;
        int c8 = idx & 15;
        cp_async16(smem_u32(&dbuf[r * SKV_STRIDE + c8 * 8]),
                   &src[(size_t)(n0 + r) * FD + d0 + c8 * 8]);
    }
}

// ---------------------------------------------------------------------------
// Kernel 0: fp32 -> fp16 conversion of x and W (Wq pre-scaled by QSCALE).
// Each thread converts one float4 -> half4.
// ---------------------------------------------------------------------------
#define X_UNITS (MTOT * DIN / 4)         // 1048576
#define W_UNITS (DIN * DOUT / 4)         // 65536
#define CV_UNITS (X_UNITS + 3 * W_UNITS) // 1245184

__global__ void convert_kernel(const float* __restrict__ x,
                               const float* __restrict__ Wq,
                               const float* __restrict__ Wk,
                               const float* __restrict__ Wv) {
    int u = blockIdx.x * blockDim.x + threadIdx.x;
    if (u >= CV_UNITS) {
        return;
    }
    if (u < X_UNITS) {
        float4 v = ((const float4*)x)[u];
        __half2 p0 = __floats2half2_rn(v.x, v.y);
        __half2 p1 = __floats2half2_rn(v.z, v.w);
        *(__half2*)&g_X16[(size_t)u * 4]     = p0;
        *(__half2*)&g_X16[(size_t)u * 4 + 2] = p1;
        return;
    }
    int w = u - X_UNITS;
    int which = w / W_UNITS;
    int e = w - which * W_UNITS;
    const float* W = (which == 0) ? Wq : ((which == 1) ? Wk : Wv);
    float sc = (which == 0) ? QSCALE : 1.0f;
    float4 v = ((const float4*)W)[e];
    __half2 p0 = __floats2half2_rn(v.x * sc, v.y * sc);
    __half2 p1 = __floats2half2_rn(v.z * sc, v.w * sc);
    *(__half2*)&g_W16[which][(size_t)e * 4]     = p0;
    *(__half2*)&g_W16[which][(size_t)e * 4 + 2] = p1;
}

// ---------------------------------------------------------------------------
// Kernel 1: projections from fp16 inputs.  out = x16 @ W16  (fp16 out)
// 128x256 tile, 512 threads, warp tile 32x64, 2-stage cp.async.
// ---------------------------------------------------------------------------
__global__ void __launch_bounds__(PTHREADS, 1)
proj_kernel() {
    extern __shared__ char sm[];

    const int which = blockIdx.z;
    const __half* X = g_X16;
    const __half* W = g_W16[which];
    __half* outbuf = (which == 0) ? g_Q : ((which == 1) ? g_K : g_V);

    const int m0 = blockIdx.y * PBM;
    const int n0 = blockIdx.x * PBN;
    const int tid = threadIdx.x;
    const int wid = tid >> 5;
    const int lane = tid & 31;
    const int wr = wid >> 2;     // 0..3 (32-row slab)
    const int wc = wid & 3;      // 0..3 (64-col slab)

    wmma::fragment<wmma::accumulator, 16, 16, 16, float> acc[2][4];
#pragma unroll
    for (int i = 0; i < 2; i++) {
#pragma unroll
        for (int j = 0; j < 4; j++) {
            wmma::fill_fragment(acc[i][j], 0.0f);
        }
    }

    // stage pointers
    __half* sA0 = (__half*)sm;
    __half* sB0 = (__half*)(sm + PA_BYTES);
    __half* sA1 = (__half*)(sm + P_STAGE);
    __half* sB1 = (__half*)(sm + P_STAGE + PA_BYTES);

    // prologue: stage 0, k=0.  A: 512 uint4 (1/thread). B: 1024 uint4 (2/thread).
    {
        int r = tid >> 2;
        int g = tid & 3;
        cp_async16(smem_u32(&sA0[r * PA_STRIDE + g * 8]),
                   &X[(size_t)(m0 + r) * DIN + g * 8]);
    }
#pragma unroll
    for (int it = 0; it < 2; it++) {
        int u = tid + it * PTHREADS;
        int r = u >> 5;
        int g = u & 31;
        cp_async16(smem_u32(&sB0[r * PB_STRIDE + g * 8]),
                   &W[(size_t)r * DOUT + n0 + g * 8]);
    }
    cp_commit();

    const int NK = DIN / PBK;   // 16
    for (int kt = 0; kt < NK; kt++) {
        __half* sA = (kt & 1) ? sA1 : sA0;
        __half* sB = (kt & 1) ? sB1 : sB0;
        if (kt + 1 < NK) {
            __half* nA = (kt & 1) ? sA0 : sA1;
            __half* nB = (kt & 1) ? sB0 : sB1;
            const int k1 = (kt + 1) * PBK;
            {
                int r = tid >> 2;
                int g = tid & 3;
                cp_async16(smem_u32(&nA[r * PA_STRIDE + g * 8]),
                           &X[(size_t)(m0 + r) * DIN + k1 + g * 8]);
            }
#pragma unroll
            for (int it = 0; it < 2; it++) {
                int u = tid + it * PTHREADS;
                int r = u >> 5;
                int g = u & 31;
                cp_async16(smem_u32(&nB[r * PB_STRIDE + g * 8]),
                           &W[(size_t)(k1 + r) * DOUT + n0 + g * 8]);
            }
        }
        cp_commit();
        cp_wait1();
        __syncthreads();

#pragma unroll
        for (int kk = 0; kk < PBK; kk += 16) {
            wmma::fragment<wmma::matrix_a, 16, 16, 16, __half, wmma::row_major> af[2];
#pragma unroll
            for (int i = 0; i < 2; i++) {
                wmma::load_matrix_sync(af[i],
                    &sA[(wr * 32 + i * 16) * PA_STRIDE + kk], PA_STRIDE);
            }
#pragma unroll
            for (int j = 0; j < 4; j++) {
                wmma::fragment<wmma::matrix_b, 16, 16, 16, __half, wmma::row_major> bf;
                wmma::load_matrix_sync(bf,
                    &sB[kk * PB_STRIDE + wc * 64 + j * 16], PB_STRIDE);
#pragma unroll
                for (int i = 0; i < 2; i++) {
                    wmma::mma_sync(acc[i][j], af[i], bf, acc[i][j]);
                }
            }
        }
        __syncthreads();
    }

    // epilogue: stage through smem, convert to fp16
    float* stage = (float*)sm + wid * 320;   // 16 warps x 16x20 floats
#pragma unroll
    for (int i = 0; i < 2; i++) {
#pragma unroll
        for (int j = 0; j < 4; j++) {
            wmma::store_matrix_sync(stage, acc[i][j], 20, wmma::mem_row_major);
            __syncwarp();
#pragma unroll
            for (int q = 0; q < 8; q++) {
                int e = lane * 8 + q;
                int r = e >> 4;
                int c = e & 15;
                size_t go = (size_t)(m0 + wr * 32 + i * 16 + r) * DOUT + (n0 + wc * 64 + j * 16 + c);
                outbuf[go] = __float2half(stage[r * 20 + c]);
            }
            __syncwarp();
        }
    }
}

// ---------------------------------------------------------------------------
// Kernel 2: fused flash attention (R9 proven config).  O = softmax(Q K^T) V.
// Grid (SEQ/FBM, BATCH), 8 warps: rg = wid>>1, cg = wid&1.
// ---------------------------------------------------------------------------
__global__ void __launch_bounds__(FTHREADS, 1)
flash_kernel(float* __restrict__ out) {
    extern __shared__ char smem[];
    __half* sQ  = (__half*)(smem + SQ_OFF);
    __half* sP  = (__half*)(smem + SP_OFF);
    float* mrun = (float*)(smem + MRUN_OFF);
    float* lrun = (float*)(smem + LRUN_OFF);
    float* wmax = (float*)(smem + WMAX_OFF);
    float* wsum = (float*)(smem + WSUM_OFF);

    const int b = blockIdx.y;
    const int m_base = blockIdx.x * FBM;
    const int tid = threadIdx.x;
    const int wid = tid >> 5;
    const int lane = tid & 31;
    const int rg = wid >> 1;
    const int cg = wid & 1;

    const __half* Qb = g_Q + (size_t)b * SEQ * FD;
    const __half* Kb = g_K + (size_t)b * SEQ * FD;
    const __half* Vb = g_V + (size_t)b * SEQ * FD;

    if (tid < 64) {
        mrun[tid] = -1e30f;
        lrun[tid] = 0.0f;
    }

#pragma unroll
    for (int it = 0; it < 16; it++) {
        int idx = tid + it * FTHREADS;
        int r = idx >> 6;
        int c8 = idx & 63;
        cp_async16(smem_u32(&sQ[r * SQ_STRIDE + c8 * 8]),
                   &Qb[(size_t)(m_base + r) * FD + c8 * 8]);
    }
    cp_commit();

    load_chunk(smem, Kb, Vb, tid, 0, 0);
    cp_commit();
    load_chunk(smem, Kb, Vb, tid, 0, 1);
    cp_commit();

    float o[32][4];
#pragma unroll
    for (int i = 0; i < 32; i++) {
#pragma unroll
        for (int e = 0; e < 4; e++) {
            o[i][e] = 0.0f;
        }
    }

    const int r0 = rg * 16 + (lane >> 2);
    const int r1 = r0 + 8;

    for (int j = 0; j < NBLK; j++) {
        float s[4][4];
#pragma unroll
        for (int t = 0; t < 4; t++) {
#pragma unroll
            for (int e = 0; e < 4; e++) {
                s[t][e] = 0.0f;
            }
        }

#pragma unroll
        for (int cc = 0; cc < 8; cc++) {
            cp_wait1();
            __syncthreads();

            int pj = j;
            int pc = cc + 2;
            if (pc >= 8) {
                pj = j + 1;
                pc = pc - 8;
            }
            if (pj < NBLK) {
                load_chunk(smem, Kb, Vb, tid, pj, pc);
            }
            cp_commit();

            const __half* buf = (const __half*)(smem + SKV_OFF + (size_t)(cc & 3) * SKV_BUF_BYTES);

            if (cc < 4) {
#pragma unroll
                for (int ks = 0; ks < 8; ks++) {
                    uint32_t a0, a1, a2, a3;
                    int arow = rg * 16 + (lane & 15);
                    int acol = cc * 128 + ks * 16 + ((lane & 16) >> 1);
                    ldm_x4(a0, a1, a2, a3, smem_u32(&sQ[arow * SQ_STRIDE + acol]));
#pragma unroll
                    for (int nt2 = 0; nt2 < 2; nt2++) {
                        uint32_t b0, b1, b2, b3;
                        int brow = cg * 32 + nt2 * 16 + (lane & 7) + ((lane & 16) >> 1);
                        int bcol = ks * 16 + (lane & 8);
                        ldm_x4(b0, b1, b2, b3, smem_u32(&buf[brow * SKV_STRIDE + bcol]));
                        mma16816(s[2 * nt2],     a0, a1, a2, a3, b0, b1);
                        mma16816(s[2 * nt2 + 1], a0, a1, a2, a3, b2, b3);
                    }
                }
                if (cc == 3) {
                    float mx0 = -1e30f;
                    float mx1 = -1e30f;
#pragma unroll
                    for (int t = 0; t < 4; t++) {
                        mx0 = fmaxf(mx0, fmaxf(s[t][0], s[t][1]));
                        mx1 = fmaxf(mx1, fmaxf(s[t][2], s[t][3]));
                    }
                    mx0 = fmaxf(mx0, __shfl_xor_sync(0xffffffffu, mx0, 1));
                    mx0 = fmaxf(mx0, __shfl_xor_sync(0xffffffffu, mx0, 2));
                    mx1 = fmaxf(mx1, __shfl_xor_sync(0xffffffffu, mx1, 1));
                    mx1 = fmaxf(mx1, __shfl_xor_sync(0xffffffffu, mx1, 2));
                    if ((lane & 3) == 0) {
                        wmax[cg * 64 + r0] = mx0;
                        wmax[cg * 64 + r1] = mx1;
                    }
                    __syncthreads();
                    float mo0 = mrun[r0];
                    float mo1 = mrun[r1];
                    float mn0 = fmaxf(mo0, fmaxf(wmax[r0], wmax[64 + r0]));
                    float mn1 = fmaxf(mo1, fmaxf(wmax[r1], wmax[64 + r1]));
                    float al0 = __expf(mo0 - mn0);
                    float al1 = __expf(mo1 - mn1);
                    float sum0 = 0.0f;
                    float sum1 = 0.0f;
#pragma unroll
                    for (int t = 0; t < 4; t++) {
                        float p00 = __expf(s[t][0] - mn0);
                        float p01 = __expf(s[t][1] - mn0);
                        float p10 = __expf(s[t][2] - mn1);
                        float p11 = __expf(s[t][3] - mn1);
                        sum0 += p00 + p01;
                        sum1 += p10 + p11;
                        int col = cg * 32 + t * 8 + 2 * (lane & 3);
                        *(__half2*)&sP[r0 * SP_STRIDE + col] = __floats2half2_rn(p00, p01);
                        *(__half2*)&sP[r1 * SP_STRIDE + col] = __floats2half2_rn(p10, p11);
                    }
#pragma unroll
                    for (int i = 0; i < 32; i++) {
                        o[i][0] *= al0;
                        o[i][1] *= al0;
                        o[i][2] *= al1;
                        o[i][3] *= al1;
                    }
                    sum0 += __shfl_xor_sync(0xffffffffu, sum0, 1);
                    sum0 += __shfl_xor_sync(0xffffffffu, sum0, 2);
                    sum1 += __shfl_xor_sync(0xffffffffu, sum1, 1);
                    sum1 += __shfl_xor_sync(0xffffffffu, sum1, 2);
                    if ((lane & 3) == 0) {
                        wsum[cg * 64 + r0] = sum0;
                        wsum[cg * 64 + r1] = sum1;
                    }
                    __syncthreads();
                    if (cg == 0 && (lane & 3) == 0) {
                        lrun[r0] = lrun[r0] * al0 + wsum[r0] + wsum[64 + r0];
                        lrun[r1] = lrun[r1] * al1 + wsum[r1] + wsum[64 + r1];
                        mrun[r0] = mn0;
                        mrun[r1] = mn1;
                    }
                }
            } else {
                const int c2 = cc - 4;
#pragma unroll
                for (int ks = 0; ks < 4; ks++) {
                    uint32_t a0, a1, a2, a3;
                    int arow = rg * 16 + (lane & 15);
                    int acol = ks * 16 + ((lane & 16) >> 1);
                    ldm_x4(a0, a1, a2, a3, smem_u32(&sP[arow * SP_STRIDE + acol]));
#pragma unroll
                    for (int nt2 = 0; nt2 < 4; nt2++) {
                        uint32_t b0, b1, b2, b3;
                        int brow = ks * 16 + (lane & 15);
                        int bcol = cg * 64 + nt2 * 16 + ((lane & 16) >> 1);
                        ldm_x4_t(b0, b1, b2, b3, smem_u32(&buf[brow * SKV_STRIDE + bcol]));
                        int t = c2 * 8 + nt2 * 2;
                        mma16816(o[t],     a0, a1, a2, a3, b0, b1);
                        mma16816(o[t + 1], a0, a1, a2, a3, b2, b3);
                    }
                }
            }
        }
    }

    __syncthreads();
    float inv0 = 1.0f / lrun[r0];
    float inv1 = 1.0f / lrun[r1];
    float* Ob = out + ((size_t)b * SEQ + m_base) * FD;
#pragma unroll
    for (int c2 = 0; c2 < 4; c2++) {
#pragma unroll
        for (int nt = 0; nt < 8; nt++) {
            int t = c2 * 8 + nt;
            int col = c2 * 128 + cg * 64 + nt * 8 + 2 * (lane & 3);
            *(float2*)&Ob[(size_t)r0 * FD + col] = make_float2(o[t][0] * inv0, o[t][1] * inv0);
            *(float2*)&Ob[(size_t)r1 * FD + col] = make_float2(o[t][2] * inv1, o[t][3] * inv1);
        }
    }
}

// ---------------------------------------------------------------------------
extern "C" void kernel_launch(void* const* d_in, const int* in_sizes, int n_in,
                              void* d_out, int out_size) {
    const float* x  = (const float*)d_in[0];
    const float* Wq = (const float*)d_in[1];
    const float* Wk = (const float*)d_in[2];
    const float* Wv = (const float*)d_in[3];
    float* out = (float*)d_out;

    cudaFuncSetAttribute(proj_kernel, cudaFuncAttributeMaxDynamicSharedMemorySize, P_SMEM);
    cudaFuncSetAttribute(flash_kernel, cudaFuncAttributeMaxDynamicSharedMemorySize, SMEM_TOTAL);

    convert_kernel<<<(CV_UNITS + 255) / 256, 256>>>(x, Wq, Wk, Wv);

    dim3 gproj(DOUT / PBN, MTOT / PBM, 3);   // (2, 64, 3)
    proj_kernel<<<gproj, PTHREADS, P_SMEM>>>();

    dim3 gflash(SEQ / FBM, BATCH);           // (64, 2)
    flash_kernel<<<gflash, FTHREADS, SMEM_TOTAL>>>(out);
}

// round 12
// speedup vs baseline: 1.2790x; 1.0042x over previous
#include <cuda_runtime.h>
#include <cuda_fp16.h>
#include <cstdint>
#include <mma.h>

using namespace nvcuda;

// Problem dims
#define BATCH   2
#define SEQ     4096
#define DIN     512
#define DOUT    512
#define MTOT    (BATCH * SEQ)
#define QSCALE  0.04419417382415922f   // 1/sqrt(512)

// Projection GEMM tiling (R7 out_kernel proven shape)
#define PBM 128
#define PBN 128
#define PBK 64
#define PTHREADS 256

// Flash attention config (R9 proven geometry, deeper pipeline)
#define FBM 64
#define FBN 64
#define FD  512
#define FDC 128
#define NBLK (SEQ / FBN)
#define FTHREADS 256
#define NCHUNK (NBLK * 8)     // 512 global chunks

// flash smem layout (bytes) — 8 K/V buffers
#define SQ_STRIDE  520
#define SKV_STRIDE 136
#define SP_STRIDE  72
#define SQ_OFF   0
#define SQ_BYTES (FBM * SQ_STRIDE * 2)            // 66560
#define SKV_OFF  SQ_BYTES
#define SKV_BUF_BYTES (64 * SKV_STRIDE * 2)       // 17408
#define SP_OFF   (SKV_OFF + 8 * SKV_BUF_BYTES)    // 205824
#define SP_BYTES (FBM * SP_STRIDE * 2)            // 9216
#define MRUN_OFF (SP_OFF + SP_BYTES)              // 215040
#define LRUN_OFF (MRUN_OFF + 256)
#define WMAX_OFF (LRUN_OFF + 256)
#define WSUM_OFF (WMAX_OFF + 512)
#define SMEM_TOTAL (WSUM_OFF + 512)               // 216576

// Scratch (device globals)
__device__ __align__(128) __half g_X16[(size_t)MTOT * DIN];
__device__ __align__(128) __half g_W16[3][(size_t)DIN * DOUT];
__device__ __align__(128) __half g_Q[(size_t)MTOT * DOUT];
__device__ __align__(128) __half g_K[(size_t)MTOT * DOUT];
__device__ __align__(128) __half g_V[(size_t)MTOT * DOUT];

// ---------------------------------------------------------------------------
// PTX helpers
// ---------------------------------------------------------------------------
__device__ __forceinline__ uint32_t smem_u32(const void* p) {
    return (uint32_t)__cvta_generic_to_shared(p);
}

__device__ __forceinline__ void cp_async16(uint32_t dst, const void* src) {
    asm volatile("cp.async.cg.shared.global [%0], [%1], 16;" :: "r"(dst), "l"(src));
}

__device__ __forceinline__ void cp_commit() {
    asm volatile("cp.async.commit_group;");
}

__device__ __forceinline__ void cp_wait5() {
    asm volatile("cp.async.wait_group 5;");
}

__device__ __forceinline__ void ldm_x4(uint32_t& a0, uint32_t& a1, uint32_t& a2, uint32_t& a3,
                                       uint32_t addr) {
    asm volatile("ldmatrix.sync.aligned.m8n8.x4.shared.b16 {%0,%1,%2,%3}, [%4];"
                 : "=r"(a0), "=r"(a1), "=r"(a2), "=r"(a3) : "r"(addr));
}

__device__ __forceinline__ void ldm_x4_t(uint32_t& a0, uint32_t& a1, uint32_t& a2, uint32_t& a3,
                                         uint32_t addr) {
    asm volatile("ldmatrix.sync.aligned.m8n8.x4.trans.shared.b16 {%0,%1,%2,%3}, [%4];"
                 : "=r"(a0), "=r"(a1), "=r"(a2), "=r"(a3) : "r"(addr));
}

__device__ __forceinline__ void mma16816(float* d, uint32_t a0, uint32_t a1, uint32_t a2,
                                         uint32_t a3, uint32_t b0, uint32_t b1) {
    asm volatile("mma.sync.aligned.m16n8k16.row.col.f32.f16.f16.f32 "
                 "{%0,%1,%2,%3}, {%4,%5,%6,%7}, {%8,%9}, {%0,%1,%2,%3};"
                 : "+f"(d[0]), "+f"(d[1]), "+f"(d[2]), "+f"(d[3])
                 : "r"(a0), "r"(a1), "r"(a2), "r"(a3), "r"(b0), "r"(b1));
}

// K/V chunk loader. ch 0..3 = K d-chunks (buffers 0..3), ch 4..7 = V (buffers 4..7).
__device__ __forceinline__ void load_chunk(char* sm, const __half* Kb, const __half* Vb,
                                           int tid, int j, int ch) {
    const __half* src = (ch < 4) ? Kb : Vb;
    const int d0 = (ch & 3) * FDC;
    __half* dbuf = (__half*)(sm + SKV_OFF + (size_t)ch * SKV_BUF_BYTES);
    const int n0 = j * FBN;
#pragma unroll
    for (int it = 0; it < 4; it++) {
        int idx = tid + it * FTHREADS;
        int r = idx >> 4;
        int c8 = idx & 15;
        cp_async16(smem_u32(&dbuf[r * SKV_STRIDE + c8 * 8]),
                   &src[(size_t)(n0 + r) * FD + d0 + c8 * 8]);
    }
}

// ---------------------------------------------------------------------------
// Kernel 0: fp32 -> fp16 conversion of x and W (Wq pre-scaled by QSCALE).
// ---------------------------------------------------------------------------
#define X_UNITS (MTOT * DIN / 4)
#define W_UNITS (DIN * DOUT / 4)
#define CV_UNITS (X_UNITS + 3 * W_UNITS)

__global__ void convert_kernel(const float* __restrict__ x,
                               const float* __restrict__ Wq,
                               const float* __restrict__ Wk,
                               const float* __restrict__ Wv) {
    int u = blockIdx.x * blockDim.x + threadIdx.x;
    if (u >= CV_UNITS) {
        return;
    }
    if (u < X_UNITS) {
        float4 v = ((const float4*)x)[u];
        *(__half2*)&g_X16[(size_t)u * 4]     = __floats2half2_rn(v.x, v.y);
        *(__half2*)&g_X16[(size_t)u * 4 + 2] = __floats2half2_rn(v.z, v.w);
        return;
    }
    int w = u - X_UNITS;
    int which = w / W_UNITS;
    int e = w - which * W_UNITS;
    const float* W = (which == 0) ? Wq : ((which == 1) ? Wk : Wv);
    float sc = (which == 0) ? QSCALE : 1.0f;
    float4 v = ((const float4*)W)[e];
    *(__half2*)&g_W16[which][(size_t)e * 4]     = __floats2half2_rn(v.x * sc, v.y * sc);
    *(__half2*)&g_W16[which][(size_t)e * 4 + 2] = __floats2half2_rn(v.z * sc, v.w * sc);
}

// ---------------------------------------------------------------------------
// Kernel 1: projections (R7 out_kernel proven shape, fp16 in / fp16 out).
// 128x128 tile, BK=64, register-prefetch double buffering, occ 2.
// ---------------------------------------------------------------------------
__global__ void __launch_bounds__(PTHREADS, 2) proj_kernel() {
    const int which = blockIdx.z;
    const __half* X = g_X16;
    const __half* W = g_W16[which];
    __half* outbuf = (which == 0) ? g_Q : ((which == 1) ? g_K : g_V);

    __shared__ __half sA[PBM][PBK + 8];    // X tile [m][k]
    __shared__ __half sB[PBK][PBN + 8];    // W tile [k][n]
    __shared__ float stage[8][16][20];

    const int m0 = blockIdx.y * PBM;
    const int n0 = blockIdx.x * PBN;
    const int tid = threadIdx.x;
    const int wid = tid >> 5;
    const int lane = tid & 31;
    const int wr = wid >> 2;
    const int wc = wid & 3;

    wmma::fragment<wmma::accumulator, 16, 16, 16, float> acc[4][2];
#pragma unroll
    for (int i = 0; i < 4; i++) {
#pragma unroll
        for (int j = 0; j < 2; j++) {
            wmma::fill_fragment(acc[i][j], 0.0f);
        }
    }

    // iteration 0: load directly to smem
#pragma unroll
    for (int it = 0; it < 4; it++) {
        int u = tid + it * PTHREADS;
        int ra = u >> 3;
        int ga = u & 7;
        *(uint4*)&sA[ra][ga * 8] = *(const uint4*)&X[(size_t)(m0 + ra) * DIN + ga * 8];
        int rb = u >> 4;
        int gb = u & 15;
        *(uint4*)&sB[rb][gb * 8] = *(const uint4*)&W[(size_t)rb * DOUT + n0 + gb * 8];
    }
    __syncthreads();

    uint4 pa[4];
    uint4 pb[4];

    for (int k0 = 0; k0 < DIN; k0 += PBK) {
        const int kn = k0 + PBK;
        if (kn < DIN) {
#pragma unroll
            for (int it = 0; it < 4; it++) {
                int u = tid + it * PTHREADS;
                int ra = u >> 3;
                int ga = u & 7;
                pa[it] = *(const uint4*)&X[(size_t)(m0 + ra) * DIN + kn + ga * 8];
                int rb = u >> 4;
                int gb = u & 15;
                pb[it] = *(const uint4*)&W[(size_t)(kn + rb) * DOUT + n0 + gb * 8];
            }
        }

#pragma unroll
        for (int kk = 0; kk < PBK; kk += 16) {
            wmma::fragment<wmma::matrix_a, 16, 16, 16, __half, wmma::row_major> af[4];
            wmma::fragment<wmma::matrix_b, 16, 16, 16, __half, wmma::row_major> bf[2];
#pragma unroll
            for (int i = 0; i < 4; i++) {
                wmma::load_matrix_sync(af[i], &sA[wr * 64 + i * 16][kk], PBK + 8);
            }
#pragma unroll
            for (int j = 0; j < 2; j++) {
                wmma::load_matrix_sync(bf[j], &sB[kk][wc * 32 + j * 16], PBN + 8);
            }
#pragma unroll
            for (int i = 0; i < 4; i++) {
#pragma unroll
                for (int j = 0; j < 2; j++) {
                    wmma::mma_sync(acc[i][j], af[i], bf[j], acc[i][j]);
                }
            }
        }
        __syncthreads();

        if (kn < DIN) {
#pragma unroll
            for (int it = 0; it < 4; it++) {
                int u = tid + it * PTHREADS;
                int ra = u >> 3;
                int ga = u & 7;
                *(uint4*)&sA[ra][ga * 8] = pa[it];
                int rb = u >> 4;
                int gb = u & 15;
                *(uint4*)&sB[rb][gb * 8] = pb[it];
            }
            __syncthreads();
        }
    }

#pragma unroll
    for (int i = 0; i < 4; i++) {
#pragma unroll
        for (int j = 0; j < 2; j++) {
            wmma::store_matrix_sync(&stage[wid][0][0], acc[i][j], 20, wmma::mem_row_major);
            __syncwarp();
#pragma unroll
            for (int q = 0; q < 8; q++) {
                int e = lane * 8 + q;
                int r = e >> 4;
                int c = e & 15;
                size_t go = (size_t)(m0 + wr * 64 + i * 16 + r) * DOUT + (n0 + wc * 32 + j * 16 + c);
                outbuf[go] = __float2half(stage[wid][r][c]);
            }
            __syncwarp();
        }
    }
}

// ---------------------------------------------------------------------------
// Kernel 2: fused flash attention.  O = softmax(Q K^T) V, fp32 out.
// R9 geometry (FBM=64, 8 warps rg=wid>>1, cg=wid&1), 8-buffer 6-deep pipeline.
// ---------------------------------------------------------------------------
__global__ void __launch_bounds__(FTHREADS, 1)
flash_kernel(float* __restrict__ out) {
    extern __shared__ char smem[];
    __half* sQ  = (__half*)(smem + SQ_OFF);
    __half* sP  = (__half*)(smem + SP_OFF);
    float* mrun = (float*)(smem + MRUN_OFF);
    float* lrun = (float*)(smem + LRUN_OFF);
    float* wmax = (float*)(smem + WMAX_OFF);
    float* wsum = (float*)(smem + WSUM_OFF);

    const int b = blockIdx.y;
    const int m_base = blockIdx.x * FBM;
    const int tid = threadIdx.x;
    const int wid = tid >> 5;
    const int lane = tid & 31;
    const int rg = wid >> 1;
    const int cg = wid & 1;

    const __half* Qb = g_Q + (size_t)b * SEQ * FD;
    const __half* Kb = g_K + (size_t)b * SEQ * FD;
    const __half* Vb = g_V + (size_t)b * SEQ * FD;

    if (tid < 64) {
        mrun[tid] = -1e30f;
        lrun[tid] = 0.0f;
    }

    // Q tile (one group)
#pragma unroll
    for (int it = 0; it < 16; it++) {
        int idx = tid + it * FTHREADS;
        int r = idx >> 6;
        int c8 = idx & 63;
        cp_async16(smem_u32(&sQ[r * SQ_STRIDE + c8 * 8]),
                   &Qb[(size_t)(m_base + r) * FD + c8 * 8]);
    }
    cp_commit();

    // prologue: chunks 0..5 (6 groups)
#pragma unroll
    for (int g = 0; g < 6; g++) {
        load_chunk(smem, Kb, Vb, tid, 0, g);
        cp_commit();
    }

    float o[32][4];
#pragma unroll
    for (int i = 0; i < 32; i++) {
#pragma unroll
        for (int e = 0; e < 4; e++) {
            o[i][e] = 0.0f;
        }
    }

    const int r0 = rg * 16 + (lane >> 2);
    const int r1 = r0 + 8;

    for (int j = 0; j < NBLK; j++) {
        float s[4][4];
#pragma unroll
        for (int t = 0; t < 4; t++) {
#pragma unroll
            for (int e = 0; e < 4; e++) {
                s[t][e] = 0.0f;
            }
        }

#pragma unroll
        for (int cc = 0; cc < 8; cc++) {
            cp_wait5();
            __syncthreads();

            int pg = j * 8 + cc + 6;
            if (pg < NCHUNK) {
                load_chunk(smem, Kb, Vb, tid, pg >> 3, pg & 7);
            }
            cp_commit();

            const __half* buf = (const __half*)(smem + SKV_OFF + (size_t)cc * SKV_BUF_BYTES);

            if (cc < 4) {
#pragma unroll
                for (int ks = 0; ks < 8; ks++) {
                    uint32_t a0, a1, a2, a3;
                    int arow = rg * 16 + (lane & 15);
                    int acol = cc * 128 + ks * 16 + ((lane & 16) >> 1);
                    ldm_x4(a0, a1, a2, a3, smem_u32(&sQ[arow * SQ_STRIDE + acol]));
#pragma unroll
                    for (int nt2 = 0; nt2 < 2; nt2++) {
                        uint32_t b0, b1, b2, b3;
                        int brow = cg * 32 + nt2 * 16 + (lane & 7) + ((lane & 16) >> 1);
                        int bcol = ks * 16 + (lane & 8);
                        ldm_x4(b0, b1, b2, b3, smem_u32(&buf[brow * SKV_STRIDE + bcol]));
                        mma16816(s[2 * nt2],     a0, a1, a2, a3, b0, b1);
                        mma16816(s[2 * nt2 + 1], a0, a1, a2, a3, b2, b3);
                    }
                }
                if (cc == 3) {
                    float mx0 = -1e30f;
                    float mx1 = -1e30f;
#pragma unroll
                    for (int t = 0; t < 4; t++) {
                        mx0 = fmaxf(mx0, fmaxf(s[t][0], s[t][1]));
                        mx1 = fmaxf(mx1, fmaxf(s[t][2], s[t][3]));
                    }
                    mx0 = fmaxf(mx0, __shfl_xor_sync(0xffffffffu, mx0, 1));
                    mx0 = fmaxf(mx0, __shfl_xor_sync(0xffffffffu, mx0, 2));
                    mx1 = fmaxf(mx1, __shfl_xor_sync(0xffffffffu, mx1, 1));
                    mx1 = fmaxf(mx1, __shfl_xor_sync(0xffffffffu, mx1, 2));
                    if ((lane & 3) == 0) {
                        wmax[cg * 64 + r0] = mx0;
                        wmax[cg * 64 + r1] = mx1;
                    }
                    __syncthreads();
                    float mo0 = mrun[r0];
                    float mo1 = mrun[r1];
                    float mn0 = fmaxf(mo0, fmaxf(wmax[r0], wmax[64 + r0]));
                    float mn1 = fmaxf(mo1, fmaxf(wmax[r1], wmax[64 + r1]));
                    float al0 = __expf(mo0 - mn0);
                    float al1 = __expf(mo1 - mn1);
                    float sum0 = 0.0f;
                    float sum1 = 0.0f;
#pragma unroll
                    for (int t = 0; t < 4; t++) {
                        float p00 = __expf(s[t][0] - mn0);
                        float p01 = __expf(s[t][1] - mn0);
                        float p10 = __expf(s[t][2] - mn1);
                        float p11 = __expf(s[t][3] - mn1);
                        sum0 += p00 + p01;
                        sum1 += p10 + p11;
                        int col = cg * 32 + t * 8 + 2 * (lane & 3);
                        *(__half2*)&sP[r0 * SP_STRIDE + col] = __floats2half2_rn(p00, p01);
                        *(__half2*)&sP[r1 * SP_STRIDE + col] = __floats2half2_rn(p10, p11);
                    }
#pragma unroll
                    for (int i = 0; i < 32; i++) {
                        o[i][0] *= al0;
                        o[i][1] *= al0;
                        o[i][2] *= al1;
                        o[i][3] *= al1;
                    }
                    sum0 += __shfl_xor_sync(0xffffffffu, sum0, 1);
                    sum0 += __shfl_xor_sync(0xffffffffu, sum0, 2);
                    sum1 += __shfl_xor_sync(0xffffffffu, sum1, 1);
                    sum1 += __shfl_xor_sync(0xffffffffu, sum1, 2);
                    if ((lane & 3) == 0) {
                        wsum[cg * 64 + r0] = sum0;
                        wsum[cg * 64 + r1] = sum1;
                    }
                    __syncthreads();
                    if (cg == 0 && (lane & 3) == 0) {
                        lrun[r0] = lrun[r0] * al0 + wsum[r0] + wsum[64 + r0];
                        lrun[r1] = lrun[r1] * al1 + wsum[r1] + wsum[64 + r1];
                        mrun[r0] = mn0;
                        mrun[r1] = mn1;
                    }
                }
            } else {
                const int c2 = cc - 4;
#pragma unroll
                for (int ks = 0; ks < 4; ks++) {
                    uint32_t a0, a1, a2, a3;
                    int arow = rg * 16 + (lane & 15);
                    int acol = ks * 16 + ((lane & 16) >> 1);
                    ldm_x4(a0, a1, a2, a3, smem_u32(&sP[arow * SP_STRIDE + acol]));
#pragma unroll
                    for (int nt2 = 0; nt2 < 4; nt2++) {
                        uint32_t b0, b1, b2, b3;
                        int brow = ks * 16 + (lane & 15);
                        int bcol = cg * 64 + nt2 * 16 + ((lane & 16) >> 1);
                        ldm_x4_t(b0, b1, b2, b3, smem_u32(&buf[brow * SKV_STRIDE + bcol]));
                        int t = c2 * 8 + nt2 * 2;
                        mma16816(o[t],     a0, a1, a2, a3, b0, b1);
                        mma16816(o[t + 1], a0, a1, a2, a3, b2, b3);
                    }
                }
            }
        }
    }

    __syncthreads();
    float inv0 = 1.0f / lrun[r0];
    float inv1 = 1.0f / lrun[r1];
    float* Ob = out + ((size_t)b * SEQ + m_base) * FD;
#pragma unroll
    for (int c2 = 0; c2 < 4; c2++) {
#pragma unroll
        for (int nt = 0; nt < 8; nt++) {
            int t = c2 * 8 + nt;
            int col = c2 * 128 + cg * 64 + nt * 8 + 2 * (lane & 3);
            *(float2*)&Ob[(size_t)r0 * FD + col] = make_float2(o[t][0] * inv0, o[t][1] * inv0);
            *(float2*)&Ob[(size_t)r1 * FD + col] = make_float2(o[t][2] * inv1, o[t][3] * inv1);
        }
    }
}

// ---------------------------------------------------------------------------
extern "C" void kernel_launch(void* const* d_in, const int* in_sizes, int n_in,
                              void* d_out, int out_size) {
    const float* x  = (const float*)d_in[0];
    const float* Wq = (const float*)d_in[1];
    const float* Wk = (const float*)d_in[2];
    const float* Wv = (const float*)d_in[3];
    float* out = (float*)d_out;

    cudaFuncSetAttribute(flash_kernel, cudaFuncAttributeMaxDynamicSharedMemorySize, SMEM_TOTAL);

    convert_kernel<<<(CV_UNITS + 255) / 256, 256>>>(x, Wq, Wk, Wv);

    dim3 gproj(DOUT / PBN, MTOT / PBM, 3);   // (4, 64, 3)
    proj_kernel<<<gproj, PTHREADS>>>();

    dim3 gflash(SEQ / FBM, BATCH);           // (64, 2)
    flash_kernel<<<gflash, FTHREADS, SMEM_TOTAL>>>(out);
}

// round 15
// speedup vs baseline: 1.2814x; 1.0019x over previous
#include <cuda_runtime.h>
#include <cuda_fp16.h>
#include <cstdint>
#include <mma.h>

using namespace nvcuda;

// Problem dims
#define BATCH   2
#define SEQ     4096
#define DIN     512
#define DOUT    512
#define MTOT    (BATCH * SEQ)
#define QSCALE  0.04419417382415922f   // 1/sqrt(512)

// Projection GEMM tiling (R7 proven shape)
#define PBM 128
#define PBN 128
#define PBK 64
#define PTHREADS 256

// Flash attention config (R9 proven: FBM=64, depth-2, 4 buffers)
#define FBM 64
#define FBN 64
#define FD  512
#define FDC 128
#define NBLK (SEQ / FBN)
#define FTHREADS 256

// flash smem layout (bytes)
#define SQ_STRIDE  520
#define SKV_STRIDE 136
#define SP_STRIDE  72
#define SQ_OFF   0
#define SQ_BYTES (FBM * SQ_STRIDE * 2)            // 66560
#define SKV_OFF  SQ_BYTES
#define SKV_BUF_BYTES (64 * SKV_STRIDE * 2)       // 17408
#define SP_OFF   (SKV_OFF + 4 * SKV_BUF_BYTES)    // 136192
#define SP_BYTES (FBM * SP_STRIDE * 2)            // 9216
#define MRUN_OFF (SP_OFF + SP_BYTES)
#define LRUN_OFF (MRUN_OFF + 256)
#define WMAX_OFF (LRUN_OFF + 256)
#define WSUM_OFF (WMAX_OFF + 512)
#define SMEM_TOTAL (WSUM_OFF + 512)               // 146944

// Scratch (device globals)
__device__ __align__(128) __half g_X16[(size_t)MTOT * DIN];
__device__ __align__(128) __half g_W16[3][(size_t)DIN * DOUT];
__device__ __align__(128) __half g_Q[(size_t)MTOT * DOUT];
__device__ __align__(128) __half g_K[(size_t)MTOT * DOUT];
__device__ __align__(128) __half g_V[(size_t)MTOT * DOUT];

// ---------------------------------------------------------------------------
// PTX helpers
// ---------------------------------------------------------------------------
__device__ __forceinline__ uint32_t smem_u32(const void* p) {
    return (uint32_t)__cvta_generic_to_shared(p);
}

__device__ __forceinline__ void cp_async16(uint32_t dst, const void* src) {
    asm volatile("cp.async.cg.shared.global [%0], [%1], 16;" :: "r"(dst), "l"(src));
}

__device__ __forceinline__ void cp_commit() {
    asm volatile("cp.async.commit_group;");
}

__device__ __forceinline__ void cp_wait1() {
    asm volatile("cp.async.wait_group 1;");
}

__device__ __forceinline__ void ldm_x4(uint32_t& a0, uint32_t& a1, uint32_t& a2, uint32_t& a3,
                                       uint32_t addr) {
    asm volatile("ldmatrix.sync.aligned.m8n8.x4.shared.b16 {%0,%1,%2,%3}, [%4];"
                 : "=r"(a0), "=r"(a1), "=r"(a2), "=r"(a3) : "r"(addr));
}

__device__ __forceinline__ void ldm_x4_t(uint32_t& a0, uint32_t& a1, uint32_t& a2, uint32_t& a3,
                                         uint32_t addr) {
    asm volatile("ldmatrix.sync.aligned.m8n8.x4.trans.shared.b16 {%0,%1,%2,%3}, [%4];"
                 : "=r"(a0), "=r"(a1), "=r"(a2), "=r"(a3) : "r"(addr));
}

__device__ __forceinline__ void mma16816(float* d, uint32_t a0, uint32_t a1, uint32_t a2,
                                         uint32_t a3, uint32_t b0, uint32_t b1) {
    asm volatile("mma.sync.aligned.m16n8k16.row.col.f32.f16.f16.f32 "
                 "{%0,%1,%2,%3}, {%4,%5,%6,%7}, {%8,%9}, {%0,%1,%2,%3};"
                 : "+f"(d[0]), "+f"(d[1]), "+f"(d[2]), "+f"(d[3])
                 : "r"(a0), "r"(a1), "r"(a2), "r"(a3), "r"(b0), "r"(b1));
}

// K/V chunk loader. ch 0..3 = K d-chunks, 4..7 = V d-chunks; buffer = ch&3.
__device__ __forceinline__ void load_chunk(char* sm, const __half* Kb, const __half* Vb,
                                           int tid, int j, int ch) {
    const __half* src = (ch < 4) ? Kb : Vb;
    const int d0 = (ch & 3) * FDC;
    __half* dbuf = (__half*)(sm + SKV_OFF + (size_t)(ch & 3) * SKV_BUF_BYTES);
    const int n0 = j * FBN;
#pragma unroll
    for (int it = 0; it < 4; it++) {
        int idx = tid + it * FTHREADS;
        int r = idx >> 4;
        int c8 = idx & 15;
        cp_async16(smem_u32(&dbuf[r * SKV_STRIDE + c8 * 8]),
                   &src[(size_t)(n0 + r) * FD + d0 + c8 * 8]);
    }
}

// ---------------------------------------------------------------------------
// Kernel 0: fp32 -> fp16 conversion of x and W (Wq pre-scaled by QSCALE).
// ---------------------------------------------------------------------------
#define X_UNITS (MTOT * DIN / 4)
#define W_UNITS (DIN * DOUT / 4)
#define CV_UNITS (X_UNITS + 3 * W_UNITS)

__global__ void convert_kernel(const float* __restrict__ x,
                               const float* __restrict__ Wq,
                               const float* __restrict__ Wk,
                               const float* __restrict__ Wv) {
    int u = blockIdx.x * blockDim.x + threadIdx.x;
    if (u >= CV_UNITS) {
        return;
    }
    if (u < X_UNITS) {
        float4 v = ((const float4*)x)[u];
        *(__half2*)&g_X16[(size_t)u * 4]     = __floats2half2_rn(v.x, v.y);
        *(__half2*)&g_X16[(size_t)u * 4 + 2] = __floats2half2_rn(v.z, v.w);
        return;
    }
    int w = u - X_UNITS;
    int which = w / W_UNITS;
    int e = w - which * W_UNITS;
    const float* W = (which == 0) ? Wq : ((which == 1) ? Wk : Wv);
    float sc = (which == 0) ? QSCALE : 1.0f;
    float4 v = ((const float4*)W)[e];
    *(__half2*)&g_W16[which][(size_t)e * 4]     = __floats2half2_rn(v.x * sc, v.y * sc);
    *(__half2*)&g_W16[which][(size_t)e * 4 + 2] = __floats2half2_rn(v.z * sc, v.w * sc);
}

// ---------------------------------------------------------------------------
// Kernel 1: projections (R7 proven shape, fp16 in / fp16 out).
// 128x128 tile, BK=64, register-prefetch double buffering, occ 2.
// ---------------------------------------------------------------------------
__global__ void __launch_bounds__(PTHREADS, 2) proj_kernel() {
    const int which = blockIdx.z;
    const __half* X = g_X16;
    const __half* W = g_W16[which];
    __half* outbuf = (which == 0) ? g_Q : ((which == 1) ? g_K : g_V);

    __shared__ __half sA[PBM][PBK + 8];    // X tile [m][k]
    __shared__ __half sB[PBK][PBN + 8];    // W tile [k][n]
    __shared__ float stage[8][16][20];

    const int m0 = blockIdx.y * PBM;
    const int n0 = blockIdx.x * PBN;
    const int tid = threadIdx.x;
    const int wid = tid >> 5;
    const int lane = tid & 31;
    const int wr = wid >> 2;
    const int wc = wid & 3;

    wmma::fragment<wmma::accumulator, 16, 16, 16, float> acc[4][2];
#pragma unroll
    for (int i = 0; i < 4; i++) {
#pragma unroll
        for (int j = 0; j < 2; j++) {
            wmma::fill_fragment(acc[i][j], 0.0f);
        }
    }

#pragma unroll
    for (int it = 0; it < 4; it++) {
        int u = tid + it * PTHREADS;
        int ra = u >> 3;
        int ga = u & 7;
        *(uint4*)&sA[ra][ga * 8] = *(const uint4*)&X[(size_t)(m0 + ra) * DIN + ga * 8];
        int rb = u >> 4;
        int gb = u & 15;
        *(uint4*)&sB[rb][gb * 8] = *(const uint4*)&W[(size_t)rb * DOUT + n0 + gb * 8];
    }
    __syncthreads();

    uint4 pa[4];
    uint4 pb[4];

    for (int k0 = 0; k0 < DIN; k0 += PBK) {
        const int kn = k0 + PBK;
        if (kn < DIN) {
#pragma unroll
            for (int it = 0; it < 4; it++) {
                int u = tid + it * PTHREADS;
                int ra = u >> 3;
                int ga = u & 7;
                pa[it] = *(const uint4*)&X[(size_t)(m0 + ra) * DIN + kn + ga * 8];
                int rb = u >> 4;
                int gb = u & 15;
                pb[it] = *(const uint4*)&W[(size_t)(kn + rb) * DOUT + n0 + gb * 8];
            }
        }

#pragma unroll
        for (int kk = 0; kk < PBK; kk += 16) {
            wmma::fragment<wmma::matrix_a, 16, 16, 16, __half, wmma::row_major> af[4];
            wmma::fragment<wmma::matrix_b, 16, 16, 16, __half, wmma::row_major> bf[2];
#pragma unroll
            for (int i = 0; i < 4; i++) {
                wmma::load_matrix_sync(af[i], &sA[wr * 64 + i * 16][kk], PBK + 8);
            }
#pragma unroll
            for (int j = 0; j < 2; j++) {
                wmma::load_matrix_sync(bf[j], &sB[kk][wc * 32 + j * 16], PBN + 8);
            }
#pragma unroll
            for (int i = 0; i < 4; i++) {
#pragma unroll
                for (int j = 0; j < 2; j++) {
                    wmma::mma_sync(acc[i][j], af[i], bf[j], acc[i][j]);
                }
            }
        }
        __syncthreads();

        if (kn < DIN) {
#pragma unroll
            for (int it = 0; it < 4; it++) {
                int u = tid + it * PTHREADS;
                int ra = u >> 3;
                int ga = u & 7;
                *(uint4*)&sA[ra][ga * 8] = pa[it];
                int rb = u >> 4;
                int gb = u & 15;
                *(uint4*)&sB[rb][gb * 8] = pb[it];
            }
            __syncthreads();
        }
    }

#pragma unroll
    for (int i = 0; i < 4; i++) {
#pragma unroll
        for (int j = 0; j < 2; j++) {
            wmma::store_matrix_sync(&stage[wid][0][0], acc[i][j], 20, wmma::mem_row_major);
            __syncwarp();
#pragma unroll
            for (int q = 0; q < 8; q++) {
                int e = lane * 8 + q;
                int r = e >> 4;
                int c = e & 15;
                size_t go = (size_t)(m0 + wr * 64 + i * 16 + r) * DOUT + (n0 + wc * 32 + j * 16 + c);
                outbuf[go] = __float2half(stage[wid][r][c]);
            }
            __syncwarp();
        }
    }
}

// ---------------------------------------------------------------------------
// Kernel 2: fused flash attention (R9 proven: depth-2, 4 buffers, 282us).
// Grid (SEQ/FBM, BATCH), 8 warps: rg = wid>>1, cg = wid&1.
// ---------------------------------------------------------------------------
__global__ void __launch_bounds__(FTHREADS, 1)
flash_kernel(float* __restrict__ out) {
    extern __shared__ char smem[];
    __half* sQ  = (__half*)(smem + SQ_OFF);
    __half* sP  = (__half*)(smem + SP_OFF);
    float* mrun = (float*)(smem + MRUN_OFF);
    float* lrun = (float*)(smem + LRUN_OFF);
    float* wmax = (float*)(smem + WMAX_OFF);
    float* wsum = (float*)(smem + WSUM_OFF);

    const int b = blockIdx.y;
    const int m_base = blockIdx.x * FBM;
    const int tid = threadIdx.x;
    const int wid = tid >> 5;
    const int lane = tid & 31;
    const int rg = wid >> 1;
    const int cg = wid & 1;

    const __half* Qb = g_Q + (size_t)b * SEQ * FD;
    const __half* Kb = g_K + (size_t)b * SEQ * FD;
    const __half* Vb = g_V + (size_t)b * SEQ * FD;

    if (tid < 64) {
        mrun[tid] = -1e30f;
        lrun[tid] = 0.0f;
    }

#pragma unroll
    for (int it = 0; it < 16; it++) {
        int idx = tid + it * FTHREADS;
        int r = idx >> 6;
        int c8 = idx & 63;
        cp_async16(smem_u32(&sQ[r * SQ_STRIDE + c8 * 8]),
                   &Qb[(size_t)(m_base + r) * FD + c8 * 8]);
    }
    cp_commit();

    load_chunk(smem, Kb, Vb, tid, 0, 0);
    cp_commit();
    load_chunk(smem, Kb, Vb, tid, 0, 1);
    cp_commit();

    float o[32][4];
#pragma unroll
    for (int i = 0; i < 32; i++) {
#pragma unroll
        for (int e = 0; e < 4; e++) {
            o[i][e] = 0.0f;
        }
    }

    const int r0 = rg * 16 + (lane >> 2);
    const int r1 = r0 + 8;

    for (int j = 0; j < NBLK; j++) {
        float s[4][4];
#pragma unroll
        for (int t = 0; t < 4; t++) {
#pragma unroll
            for (int e = 0; e < 4; e++) {
                s[t][e] = 0.0f;
            }
        }

#pragma unroll
        for (int cc = 0; cc < 8; cc++) {
            cp_wait1();
            __syncthreads();

            int pj = j;
            int pc = cc + 2;
            if (pc >= 8) {
                pj = j + 1;
                pc = pc - 8;
            }
            if (pj < NBLK) {
                load_chunk(smem, Kb, Vb, tid, pj, pc);
            }
            cp_commit();

            const __half* buf = (const __half*)(smem + SKV_OFF + (size_t)(cc & 3) * SKV_BUF_BYTES);

            if (cc < 4) {
#pragma unroll
                for (int ks = 0; ks < 8; ks++) {
                    uint32_t a0, a1, a2, a3;
                    int arow = rg * 16 + (lane & 15);
                    int acol = cc * 128 + ks * 16 + ((lane & 16) >> 1);
                    ldm_x4(a0, a1, a2, a3, smem_u32(&sQ[arow * SQ_STRIDE + acol]));
#pragma unroll
                    for (int nt2 = 0; nt2 < 2; nt2++) {
                        uint32_t b0, b1, b2, b3;
                        int brow = cg * 32 + nt2 * 16 + (lane & 7) + ((lane & 16) >> 1);
                        int bcol = ks * 16 + (lane & 8);
                        ldm_x4(b0, b1, b2, b3, smem_u32(&buf[brow * SKV_STRIDE + bcol]));
                        mma16816(s[2 * nt2],     a0, a1, a2, a3, b0, b1);
                        mma16816(s[2 * nt2 + 1], a0, a1, a2, a3, b2, b3);
                    }
                }
                if (cc == 3) {
                    float mx0 = -1e30f;
                    float mx1 = -1e30f;
#pragma unroll
                    for (int t = 0; t < 4; t++) {
                        mx0 = fmaxf(mx0, fmaxf(s[t][0], s[t][1]));
                        mx1 = fmaxf(mx1, fmaxf(s[t][2], s[t][3]));
                    }
                    mx0 = fmaxf(mx0, __shfl_xor_sync(0xffffffffu, mx0, 1));
                    mx0 = fmaxf(mx0, __shfl_xor_sync(0xffffffffu, mx0, 2));
                    mx1 = fmaxf(mx1, __shfl_xor_sync(0xffffffffu, mx1, 1));
                    mx1 = fmaxf(mx1, __shfl_xor_sync(0xffffffffu, mx1, 2));
                    if ((lane & 3) == 0) {
                        wmax[cg * 64 + r0] = mx0;
                        wmax[cg * 64 + r1] = mx1;
                    }
                    __syncthreads();
                    float mo0 = mrun[r0];
                    float mo1 = mrun[r1];
                    float mn0 = fmaxf(mo0, fmaxf(wmax[r0], wmax[64 + r0]));
                    float mn1 = fmaxf(mo1, fmaxf(wmax[r1], wmax[64 + r1]));
                    float al0 = __expf(mo0 - mn0);
                    float al1 = __expf(mo1 - mn1);
                    float sum0 = 0.0f;
                    float sum1 = 0.0f;
#pragma unroll
                    for (int t = 0; t < 4; t++) {
                        float p00 = __expf(s[t][0] - mn0);
                        float p01 = __expf(s[t][1] - mn0);
                        float p10 = __expf(s[t][2] - mn1);
                        float p11 = __expf(s[t][3] - mn1);
                        sum0 += p00 + p01;
                        sum1 += p10 + p11;
                        int col = cg * 32 + t * 8 + 2 * (lane & 3);
                        *(__half2*)&sP[r0 * SP_STRIDE + col] = __floats2half2_rn(p00, p01);
                        *(__half2*)&sP[r1 * SP_STRIDE + col] = __floats2half2_rn(p10, p11);
                    }
#pragma unroll
                    for (int i = 0; i < 32; i++) {
                        o[i][0] *= al0;
                        o[i][1] *= al0;
                        o[i][2] *= al1;
                        o[i][3] *= al1;
                    }
                    sum0 += __shfl_xor_sync(0xffffffffu, sum0, 1);
                    sum0 += __shfl_xor_sync(0xffffffffu, sum0, 2);
                    sum1 += __shfl_xor_sync(0xffffffffu, sum1, 1);
                    sum1 += __shfl_xor_sync(0xffffffffu, sum1, 2);
                    if ((lane & 3) == 0) {
                        wsum[cg * 64 + r0] = sum0;
                        wsum[cg * 64 + r1] = sum1;
                    }
                    __syncthreads();
                    if (cg == 0 && (lane & 3) == 0) {
                        lrun[r0] = lrun[r0] * al0 + wsum[r0] + wsum[64 + r0];
                        lrun[r1] = lrun[r1] * al1 + wsum[r1] + wsum[64 + r1];
                        mrun[r0] = mn0;
                        mrun[r1] = mn1;
                    }
                }
            } else {
                const int c2 = cc - 4;
#pragma unroll
                for (int ks = 0; ks < 4; ks++) {
                    uint32_t a0, a1, a2, a3;
                    int arow = rg * 16 + (lane & 15);
                    int acol = ks * 16 + ((lane & 16) >> 1);
                    ldm_x4(a0, a1, a2, a3, smem_u32(&sP[arow * SP_STRIDE + acol]));
#pragma unroll
                    for (int nt2 = 0; nt2 < 4; nt2++) {
                        uint32_t b0, b1, b2, b3;
                        int brow = ks * 16 + (lane & 15);
                        int bcol = cg * 64 + nt2 * 16 + ((lane & 16) >> 1);
                        ldm_x4_t(b0, b1, b2, b3, smem_u32(&buf[brow * SKV_STRIDE + bcol]));
                        int t = c2 * 8 + nt2 * 2;
                        mma16816(o[t],     a0, a1, a2, a3, b0, b1);
                        mma16816(o[t + 1], a0, a1, a2, a3, b2, b3);
                    }
                }
            }
        }
    }

    __syncthreads();
    float inv0 = 1.0f / lrun[r0];
    float inv1 = 1.0f / lrun[r1];
    float* Ob = out + ((size_t)b * SEQ + m_base) * FD;
#pragma unroll
    for (int c2 = 0; c2 < 4; c2++) {
#pragma unroll
        for (int nt = 0; nt < 8; nt++) {
            int t = c2 * 8 + nt;
            int col = c2 * 128 + cg * 64 + nt * 8 + 2 * (lane & 3);
            *(float2*)&Ob[(size_t)r0 * FD + col] = make_float2(o[t][0] * inv0, o[t][1] * inv0);
            *(float2*)&Ob[(size_t)r1 * FD + col] = make_float2(o[t][2] * inv1, o[t][3] * inv1);
        }
    }
}

// ---------------------------------------------------------------------------
extern "C" void kernel_launch(void* const* d_in, const int* in_sizes, int n_in,
                              void* d_out, int out_size) {
    const float* x  = (const float*)d_in[0];
    const float* Wq = (const float*)d_in[1];
    const float* Wk = (const float*)d_in[2];
    const float* Wv = (const float*)d_in[3];
    float* out = (float*)d_out;

    cudaFuncSetAttribute(flash_kernel, cudaFuncAttributeMaxDynamicSharedMemorySize, SMEM_TOTAL);

    convert_kernel<<<(CV_UNITS + 255) / 256, 256>>>(x, Wq, Wk, Wv);

    dim3 gproj(DOUT / PBN, MTOT / PBM, 3);   // (4, 64, 3)
    proj_kernel<<<gproj, PTHREADS>>>();

    dim3 gflash(SEQ / FBM, BATCH);           // (64, 2)
    flash_kernel<<<gflash, FTHREADS, SMEM_TOTAL>>>(out);
}